// round 9
// baseline (speedup 1.0000x reference)
#include <cuda_runtime.h>
#include <cuda_fp16.h>
#include <math.h>
#include <stdint.h>

#define NB 4
#define NS 2048
#define NH 2048
#define NF 5632
#define NE 8
#define NT (NB * NS)   /* 8192 tokens */
#define NP (NT * 2)    /* 16384 (token, expert) pairs */

// ---------------- scratch (device globals) ----------------------------------
__device__ __half g_h1h[(size_t)NP * NF];
__device__ float  g_ho[(size_t)NP * NH];
__device__ __half g_xh[(size_t)NT * NH];
// gemm1 B: per expert, NF/8 blocks x {gate,up} x 8 rows, each row NH halfs
__device__ __half g_w1h[(size_t)NE * NF * 2 * NH];
__device__ __half g_wdh[(size_t)NE * NH * NF];
__device__ int   g_top_i[NP];
__device__ float g_top_w[NP];
__device__ int   g_pair_token[NP];
__device__ int   g_token_pair[NP];
__device__ int   g_counts[NE];
__device__ int   g_offsets[NE];
__device__ int   g_cursor[NE];

// ---------------- helpers ----------------------------------------------------
__device__ __forceinline__ uint32_t s2u(const void* p) {
    uint32_t a;
    asm("{ .reg .u64 t; cvta.to.shared.u64 t, %1; cvt.u32.u64 %0, t; }" : "=r"(a) : "l"(p));
    return a;
}
__device__ __forceinline__ void ldmx4(uint32_t* r, uint32_t a) {
    asm volatile("ldmatrix.sync.aligned.m8n8.x4.shared.b16 {%0,%1,%2,%3}, [%4];"
                 : "=r"(r[0]), "=r"(r[1]), "=r"(r[2]), "=r"(r[3]) : "r"(a));
}
__device__ __forceinline__ void mma16816(float* c, const uint32_t* a, uint32_t b0, uint32_t b1) {
    asm volatile(
        "mma.sync.aligned.m16n8k16.row.col.f32.f16.f16.f32 "
        "{%0,%1,%2,%3}, {%4,%5,%6,%7}, {%8,%9}, {%0,%1,%2,%3};"
        : "+f"(c[0]), "+f"(c[1]), "+f"(c[2]), "+f"(c[3])
        : "r"(a[0]), "r"(a[1]), "r"(a[2]), "r"(a[3]), "r"(b0), "r"(b1));
}
__device__ __forceinline__ uint32_t h2u(__half2 v) { return *reinterpret_cast<uint32_t*>(&v); }

__device__ __forceinline__ void cpa16(uint32_t dst, const void* src) {
    asm volatile("cp.async.cg.shared.global [%0], [%1], 16;" :: "r"(dst), "l"(src));
}
#define CPA_COMMIT() asm volatile("cp.async.commit_group;" ::: "memory")
#define CPA_WAIT2()  asm volatile("cp.async.wait_group 2;" ::: "memory")

// convert 8 fp32 -> 8 fp16 (uint4)
__device__ __forceinline__ uint4 cv8h(float4 a, float4 b) {
    uint4 r;
    r.x = h2u(__floats2half2_rn(a.x, a.y));
    r.y = h2u(__floats2half2_rn(a.z, a.w));
    r.z = h2u(__floats2half2_rn(b.x, b.y));
    r.w = h2u(__floats2half2_rn(b.z, b.w));
    return r;
}

// smem tile geometry: rows x 16 half (32B), padded row stride 48 bytes
// stage = two 16-wide sub-tiles: [A0|B0|A1|B1]
#define TROW 48
#define A_TB (128 * TROW)            /* 6144  */
#define B_TB (256 * TROW)            /* 12288 */
#define SUBSTAGE (A_TB + B_TB)       /* 18432 */
#define STAGE (2 * SUBSTAGE)         /* 36864 */
#define NSTAGE 4
#define GSMEM (NSTAGE * STAGE)       /* 147456 */
#define OAH 0
#define OBH A_TB

// ---------------- small kernels ---------------------------------------------
__global__ void init_k() {
    if (threadIdx.x < NE) g_counts[threadIdx.x] = 0;
}

__global__ void router_k(const float* __restrict__ x, const float* __restrict__ rW,
                         const int* __restrict__ elim_p, float* __restrict__ logits_out) {
    const int gwarp = (blockIdx.x * blockDim.x + threadIdx.x) >> 5;
    const int lane  = threadIdx.x & 31;
    if (gwarp >= NT) return;
    const float* xr = x + (size_t)gwarp * NH;
    float acc[NE];
#pragma unroll
    for (int e = 0; e < NE; ++e) acc[e] = 0.f;
    for (int h = lane; h < NH; h += 32) {
        const float xv = xr[h];
#pragma unroll
        for (int e = 0; e < NE; ++e) acc[e] = fmaf(xv, rW[e * NH + h], acc[e]);
    }
#pragma unroll
    for (int e = 0; e < NE; ++e)
#pragma unroll
        for (int o = 16; o > 0; o >>= 1) acc[e] += __shfl_xor_sync(0xffffffffu, acc[e], o);

    if (lane == 0) {
        const int elim = *elim_p;
#pragma unroll
        for (int e = 0; e < NE; ++e) if (e >= elim) acc[e] = -INFINITY;
#pragma unroll
        for (int e = 0; e < NE; ++e) logits_out[gwarp * NE + e] = acc[e];
        int i0 = 0; float v0 = acc[0];
        for (int e = 1; e < NE; ++e) if (acc[e] > v0) { v0 = acc[e]; i0 = e; }
        int i1 = -1; float v1 = -INFINITY;
        for (int e = 0; e < NE; ++e) { if (e == i0) continue; if (acc[e] > v1) { v1 = acc[e]; i1 = e; } }
        float w0, w1;
        if (i1 < 0) { i1 = (i0 + 1) & (NE - 1); w0 = 1.f; w1 = 0.f; }
        else {
            const float ex = expf(v1 - v0);
            w0 = 1.f / (1.f + ex);
            w1 = ex  / (1.f + ex);
        }
        g_top_i[gwarp * 2 + 0] = i0; g_top_i[gwarp * 2 + 1] = i1;
        g_top_w[gwarp * 2 + 0] = w0; g_top_w[gwarp * 2 + 1] = w1;
        atomicAdd(&g_counts[i0], 1);
        atomicAdd(&g_counts[i1], 1);
    }
}

__global__ void scan_k() {
    if (threadIdx.x == 0) {
        int o = 0;
        for (int e = 0; e < NE; ++e) { g_offsets[e] = o; o += g_counts[e]; g_cursor[e] = 0; }
    }
}

__global__ void scatter_k() {
    const int t = blockIdx.x * blockDim.x + threadIdx.x;
    if (t >= NT) return;
#pragma unroll
    for (int k = 0; k < 2; ++k) {
        const int e   = g_top_i[t * 2 + k];
        const int pos = g_offsets[e] + atomicAdd(&g_cursor[e], 1);
        g_pair_token[pos]       = t;
        g_token_pair[t * 2 + k] = pos;
    }
}

// ---------------- conversion kernels ----------------------------------------
// gate/up -> g_w1h interleaved: row = (e*(NF/8) + f/8)*16 + m*8 + (f&7)
__global__ void cvtw1_k(const float* __restrict__ gW, const float* __restrict__ uW) {
    const size_t idx = (size_t)blockIdx.x * blockDim.x + threadIdx.x;
    if (idx >= (size_t)NE * NF * (NH / 8)) return;
    const int hb  = idx % (NH / 8);
    const int f   = (idx / (NH / 8)) % NF;
    const int e   = idx / ((size_t)NF * (NH / 8));
    const size_t src = ((size_t)e * NF + f) * NH + hb * 8;
    const size_t rowg = ((size_t)e * (NF / 8) + (f >> 3)) * 16 + (f & 7);
    {
        float4 a = *(const float4*)(gW + src), b = *(const float4*)(gW + src + 4);
        *(uint4*)(g_w1h + rowg * NH + hb * 8) = cv8h(a, b);
    }
    {
        float4 a = *(const float4*)(uW + src), b = *(const float4*)(uW + src + 4);
        *(uint4*)(g_w1h + (rowg + 8) * NH + hb * 8) = cv8h(a, b);
    }
}

__global__ void cvtwd_k(const float* __restrict__ dW) {
    const size_t idx = (size_t)blockIdx.x * blockDim.x + threadIdx.x;
    if (idx >= (size_t)NE * NH * (NF / 8)) return;
    const size_t src = idx * 8;
    float4 a = *(const float4*)(dW + src), b = *(const float4*)(dW + src + 4);
    *(uint4*)(g_wdh + src) = cv8h(a, b);
}

__global__ void cvtx_k(const float* __restrict__ x) {
    const size_t idx = (size_t)blockIdx.x * blockDim.x + threadIdx.x;
    if (idx >= (size_t)NT * (NH / 8)) return;
    const size_t src = idx * 8;
    float4 a = *(const float4*)(x + src), b = *(const float4*)(x + src + 4);
    *(uint4*)(g_xh + src) = cv8h(a, b);
}

// ---------------- GEMM1: fp16 mma, cp.async pipeline, BK=32 ------------------
// CTA tile: 128 pairs x 128 F-cols (256 n-space, gate/up interleaved).
__global__ void __launch_bounds__(256)
gemm1_k() {
    const int e   = blockIdx.z;
    const int cnt = g_counts[e];
    const int m0  = blockIdx.x * 128;
    if (m0 >= cnt) return;
    const int off = g_offsets[e];
    const int f0  = blockIdx.y * 128;

    extern __shared__ char smem[];
    const uint32_t sb = s2u(smem);
    const int tid  = threadIdx.x;
    const int wid  = tid >> 5;
    const int lane = tid & 31;
    const int wm = wid >> 2, wn = wid & 3;

    // loader mapping: each thread copies 16B segments (row, half) per sub-tile
    const int lrow = tid >> 1;
    const int half = tid & 1;
    int mrow = m0 + lrow; if (mrow >= cnt) mrow = cnt - 1;
    const int tok = g_pair_token[off + mrow];
    const __half* axh = g_xh + (size_t)tok * NH + half * 8;
    const size_t bbase = ((size_t)e * (NF / 8) + (f0 >> 3)) * 16;
    const __half* bw0 = g_w1h + (bbase + lrow) * NH + half * 8;
    const __half* bw1 = g_w1h + (bbase + 128 + lrow) * NH + half * 8;
    const uint32_t a_soff  = lrow * TROW + half * 16;
    const uint32_t b_soff0 = lrow * TROW + half * 16;
    const uint32_t b_soff1 = (128 + lrow) * TROW + half * 16;

    float acc[4][8][4];
#pragma unroll
    for (int i = 0; i < 4; ++i)
#pragma unroll
        for (int j = 0; j < 8; ++j)
#pragma unroll
            for (int q = 0; q < 4; ++q) acc[i][j][q] = 0.f;

    const int NCH = NH / 32;   // 64
    // prologue: issue stages 0..2
#pragma unroll
    for (int s = 0; s < 3; ++s) {
        const uint32_t st = sb + s * STAGE;
        const int k = s * 32;
#pragma unroll
        for (int sub = 0; sub < 2; ++sub) {
            const uint32_t su = st + sub * SUBSTAGE;
            const int ks = k + sub * 16;
            cpa16(su + OAH + a_soff, axh + ks);
            cpa16(su + OBH + b_soff0, bw0 + ks);
            cpa16(su + OBH + b_soff1, bw1 + ks);
        }
        CPA_COMMIT();
    }

    const uint32_t afr = (wm * 64 + (lane & 15)) * TROW + (lane >> 4) * 16;
    const uint32_t bfr = (wn * 64 + ((lane >> 4) << 3) + (lane & 7)) * TROW + ((lane >> 3) & 1) * 16;

    for (int c = 0; c < NCH; ++c) {
        CPA_WAIT2();
        __syncthreads();

        // issue chunk c+3 into slot (c+3)%4 (that slot's reads finished at iter c-1)
        if (c + 3 < NCH) {
            const uint32_t st = sb + ((c + 3) & 3) * STAGE;
            const int k = (c + 3) * 32;
#pragma unroll
            for (int sub = 0; sub < 2; ++sub) {
                const uint32_t su = st + sub * SUBSTAGE;
                const int ks = k + sub * 16;
                cpa16(su + OAH + a_soff, axh + ks);
                cpa16(su + OBH + b_soff0, bw0 + ks);
                cpa16(su + OBH + b_soff1, bw1 + ks);
            }
        }
        CPA_COMMIT();

        const uint32_t stg = sb + (c & 3) * STAGE;
#pragma unroll
        for (int sub = 0; sub < 2; ++sub) {
            const uint32_t st = stg + sub * SUBSTAGE;
            uint32_t ah[4][4];
#pragma unroll
            for (int i = 0; i < 4; ++i)
                ldmx4(ah[i], st + OAH + afr + i * 16 * TROW);
#pragma unroll
            for (int jp = 0; jp < 4; ++jp) {
                uint32_t bh[4];
                ldmx4(bh, st + OBH + bfr + jp * 16 * TROW);
#pragma unroll
                for (int i = 0; i < 4; ++i) {
                    mma16816(acc[i][2 * jp],     ah[i], bh[0], bh[1]);
                    mma16816(acc[i][2 * jp + 1], ah[i], bh[2], bh[3]);
                }
            }
        }
    }

    // epilogue: silu(gate)*up -> h1 as fp16
#pragma unroll
    for (int i = 0; i < 4; ++i) {
        const int r0l = wm * 64 + i * 16 + (lane >> 2);
        const int r1l = r0l + 8;
#pragma unroll
        for (int jp = 0; jp < 4; ++jp) {
            const int col = f0 + (wn * 4 + jp) * 8 + (lane & 3) * 2;
            const float* gv = acc[i][2 * jp];
            const float* uv = acc[i][2 * jp + 1];
            if (m0 + r0l < cnt) {
                float o0 = (gv[0] / (1.f + __expf(-gv[0]))) * uv[0];
                float o1 = (gv[1] / (1.f + __expf(-gv[1]))) * uv[1];
                const size_t p = (size_t)(off + m0 + r0l) * NF + col;
                *(uint32_t*)(g_h1h + p) = h2u(__floats2half2_rn(o0, o1));
            }
            if (m0 + r1l < cnt) {
                float o2 = (gv[2] / (1.f + __expf(-gv[2]))) * uv[2];
                float o3 = (gv[3] / (1.f + __expf(-gv[3]))) * uv[3];
                const size_t p = (size_t)(off + m0 + r1l) * NF + col;
                *(uint32_t*)(g_h1h + p) = h2u(__floats2half2_rn(o2, o3));
            }
        }
    }
}

// ---------------- GEMM2: fp16 mma, cp.async pipeline, BK=32 ------------------
// CTA tile: 128 pairs x 256 H-cols.
__global__ void __launch_bounds__(256)
gemm2_k(const float* __restrict__ db) {
    const int e   = blockIdx.z;
    const int cnt = g_counts[e];
    const int m0  = blockIdx.x * 128;
    if (m0 >= cnt) return;
    const int off = g_offsets[e];
    const int n0  = blockIdx.y * 256;

    extern __shared__ char smem[];
    const uint32_t sb = s2u(smem);
    const int tid  = threadIdx.x;
    const int wid  = tid >> 5;
    const int lane = tid & 31;
    const int wm = wid >> 2, wn = wid & 3;

    const int lrow = tid >> 1;
    const int half = tid & 1;
    int mrow = m0 + lrow; if (mrow >= cnt) mrow = cnt - 1;
    const __half* axh = g_h1h + (size_t)(off + mrow) * NF + half * 8;
    const __half* bw0 = g_wdh + ((size_t)e * NH + n0 + lrow) * NF + half * 8;
    const __half* bw1 = g_wdh + ((size_t)e * NH + n0 + 128 + lrow) * NF + half * 8;
    const uint32_t a_soff  = lrow * TROW + half * 16;
    const uint32_t b_soff0 = lrow * TROW + half * 16;
    const uint32_t b_soff1 = (128 + lrow) * TROW + half * 16;

    float acc[4][8][4];
#pragma unroll
    for (int i = 0; i < 4; ++i)
#pragma unroll
        for (int j = 0; j < 8; ++j)
#pragma unroll
            for (int q = 0; q < 4; ++q) acc[i][j][q] = 0.f;

    const int NCH = NF / 32;   // 176
#pragma unroll
    for (int s = 0; s < 3; ++s) {
        const uint32_t st = sb + s * STAGE;
        const int k = s * 32;
#pragma unroll
        for (int sub = 0; sub < 2; ++sub) {
            const uint32_t su = st + sub * SUBSTAGE;
            const int ks = k + sub * 16;
            cpa16(su + OAH + a_soff, axh + ks);
            cpa16(su + OBH + b_soff0, bw0 + ks);
            cpa16(su + OBH + b_soff1, bw1 + ks);
        }
        CPA_COMMIT();
    }

    const uint32_t afr = (wm * 64 + (lane & 15)) * TROW + (lane >> 4) * 16;
    const uint32_t bfr = (wn * 64 + ((lane >> 4) << 3) + (lane & 7)) * TROW + ((lane >> 3) & 1) * 16;

    for (int c = 0; c < NCH; ++c) {
        CPA_WAIT2();
        __syncthreads();

        if (c + 3 < NCH) {
            const uint32_t st = sb + ((c + 3) & 3) * STAGE;
            const int k = (c + 3) * 32;
#pragma unroll
            for (int sub = 0; sub < 2; ++sub) {
                const uint32_t su = st + sub * SUBSTAGE;
                const int ks = k + sub * 16;
                cpa16(su + OAH + a_soff, axh + ks);
                cpa16(su + OBH + b_soff0, bw0 + ks);
                cpa16(su + OBH + b_soff1, bw1 + ks);
            }
        }
        CPA_COMMIT();

        const uint32_t stg = sb + (c & 3) * STAGE;
#pragma unroll
        for (int sub = 0; sub < 2; ++sub) {
            const uint32_t st = stg + sub * SUBSTAGE;
            uint32_t ah[4][4];
#pragma unroll
            for (int i = 0; i < 4; ++i)
                ldmx4(ah[i], st + OAH + afr + i * 16 * TROW);
#pragma unroll
            for (int jp = 0; jp < 4; ++jp) {
                uint32_t bh[4];
                ldmx4(bh, st + OBH + bfr + jp * 16 * TROW);
#pragma unroll
                for (int i = 0; i < 4; ++i) {
                    mma16816(acc[i][2 * jp],     ah[i], bh[0], bh[1]);
                    mma16816(acc[i][2 * jp + 1], ah[i], bh[2], bh[3]);
                }
            }
        }
    }

#pragma unroll
    for (int i = 0; i < 4; ++i) {
        const int r0l = wm * 64 + i * 16 + (lane >> 2);
        const int r1l = r0l + 8;
#pragma unroll
        for (int j = 0; j < 8; ++j) {
            const int col = n0 + wn * 64 + j * 8 + (lane & 3) * 2;
            const float b0 = db[(size_t)e * NH + col];
            const float b1 = db[(size_t)e * NH + col + 1];
            if (m0 + r0l < cnt)
                *(float2*)(g_ho + (size_t)(off + m0 + r0l) * NH + col) =
                    make_float2(acc[i][j][0] + b0, acc[i][j][1] + b1);
            if (m0 + r1l < cnt)
                *(float2*)(g_ho + (size_t)(off + m0 + r1l) * NH + col) =
                    make_float2(acc[i][j][2] + b0, acc[i][j][3] + b1);
        }
    }
}

// ---------------- combine ----------------------------------------------------
__global__ void combine_k(const float* __restrict__ res, float* __restrict__ out) {
    const int idx = blockIdx.x * blockDim.x + threadIdx.x;
    const int NV  = NT * NH / 4;
    if (idx >= NV) return;
    const int t = idx >> 9;
    const int c = idx & 511;
    const int p0 = g_token_pair[2 * t + 0];
    const int p1 = g_token_pair[2 * t + 1];
    const float w0 = g_top_w[2 * t + 0];
    const float w1 = g_top_w[2 * t + 1];
    const float4 r = ((const float4*)res)[idx];
    const float4 a = *((const float4*)(g_ho + (size_t)p0 * NH) + c);
    const float4 b = *((const float4*)(g_ho + (size_t)p1 * NH) + c);
    float4 o;
    o.x = r.x + w0 * a.x + w1 * b.x;
    o.y = r.y + w0 * a.y + w1 * b.y;
    o.z = r.z + w0 * a.z + w1 * b.z;
    o.w = r.w + w0 * a.w + w1 * b.w;
    ((float4*)out)[idx] = o;
}

// ---------------- launch ----------------------------------------------------
extern "C" void kernel_launch(void* const* d_in, const int* in_sizes, int n_in,
                              void* d_out, int out_size) {
    const float* x    = (const float*)d_in[0];
    const float* res  = (const float*)d_in[1];
    const float* rW   = (const float*)d_in[2];
    const float* gW   = (const float*)d_in[3];
    const float* uW   = (const float*)d_in[4];
    const float* dW   = (const float*)d_in[5];
    const float* db   = (const float*)d_in[6];
    const int*   elim = (const int*)d_in[7];

    float* out    = (float*)d_out;
    float* logits = out + (size_t)NT * NH;

    cudaFuncSetAttribute(gemm1_k, cudaFuncAttributeMaxDynamicSharedMemorySize, GSMEM);
    cudaFuncSetAttribute(gemm2_k, cudaFuncAttributeMaxDynamicSharedMemorySize, GSMEM);

    init_k<<<1, 32>>>();
    router_k<<<NT / 8, 256>>>(x, rW, elim, logits);
    scan_k<<<1, 32>>>();
    scatter_k<<<NT / 256, 256>>>();

    const size_t nw1 = (size_t)NE * NF * (NH / 8);
    cvtw1_k<<<(unsigned)((nw1 + 255) / 256), 256>>>(gW, uW);
    const size_t nwd = (size_t)NE * NH * (NF / 8);
    cvtwd_k<<<(unsigned)((nwd + 255) / 256), 256>>>(dW);
    const size_t nx = (size_t)NT * (NH / 8);
    cvtx_k<<<(unsigned)((nx + 255) / 256), 256>>>(x);

    gemm1_k<<<dim3(NT / 128, NF / 128, NE), 256, GSMEM>>>();
    gemm2_k<<<dim3(NT / 128, NH / 256, NE), 256, GSMEM>>>(db);
    combine_k<<<(NT * NH / 4 + 255) / 256, 256>>>(res, out);
}

// round 12
// speedup vs baseline: 1.0340x; 1.0340x over previous
#include <cuda_runtime.h>
#include <cuda_fp16.h>
#include <math.h>
#include <stdint.h>

#define NB 4
#define NS 2048
#define NH 2048
#define NF 5632
#define NE 8
#define NT (NB * NS)   /* 8192 tokens */
#define NP (NT * 2)    /* 16384 (token, expert) pairs */

// ---------------- scratch (device globals) ----------------------------------
__device__ __half g_h1h[(size_t)NP * NF];
__device__ __half g_hoh[(size_t)NP * NH];
__device__ __half g_xh[(size_t)NT * NH];
// gemm1 B: per expert, NF/8 blocks x {gate,up} x 8 rows, each row NH halfs
__device__ __half g_w1h[(size_t)NE * NF * 2 * NH];
__device__ __half g_wdh[(size_t)NE * NH * NF];
__device__ int   g_top_i[NP];
__device__ float g_top_w[NP];
__device__ int   g_pair_token[NP];
__device__ int   g_token_pair[NP];
__device__ int   g_counts[NE];
__device__ int   g_offsets[NE];
__device__ int   g_cursor[NE];

// ---------------- helpers ----------------------------------------------------
__device__ __forceinline__ uint32_t s2u(const void* p) {
    uint32_t a;
    asm("{ .reg .u64 t; cvta.to.shared.u64 t, %1; cvt.u32.u64 %0, t; }" : "=r"(a) : "l"(p));
    return a;
}
__device__ __forceinline__ void ldmx4(uint32_t* r, uint32_t a) {
    asm volatile("ldmatrix.sync.aligned.m8n8.x4.shared.b16 {%0,%1,%2,%3}, [%4];"
                 : "=r"(r[0]), "=r"(r[1]), "=r"(r[2]), "=r"(r[3]) : "r"(a));
}
__device__ __forceinline__ void mma16816(float* c, const uint32_t* a, uint32_t b0, uint32_t b1) {
    asm volatile(
        "mma.sync.aligned.m16n8k16.row.col.f32.f16.f16.f32 "
        "{%0,%1,%2,%3}, {%4,%5,%6,%7}, {%8,%9}, {%0,%1,%2,%3};"
        : "+f"(c[0]), "+f"(c[1]), "+f"(c[2]), "+f"(c[3])
        : "r"(a[0]), "r"(a[1]), "r"(a[2]), "r"(a[3]), "r"(b0), "r"(b1));
}
__device__ __forceinline__ uint32_t h2u(__half2 v) { return *reinterpret_cast<uint32_t*>(&v); }

__device__ __forceinline__ void cpa16(uint32_t dst, const void* src) {
    asm volatile("cp.async.cg.shared.global [%0], [%1], 16;" :: "r"(dst), "l"(src));
}
#define CPA_COMMIT() asm volatile("cp.async.commit_group;" ::: "memory")
#define CPA_WAIT4()  asm volatile("cp.async.wait_group 4;" ::: "memory")

// convert 8 fp32 -> 8 fp16 (uint4)
__device__ __forceinline__ uint4 cv8h(float4 a, float4 b) {
    uint4 r;
    r.x = h2u(__floats2half2_rn(a.x, a.y));
    r.y = h2u(__floats2half2_rn(a.z, a.w));
    r.z = h2u(__floats2half2_rn(b.x, b.y));
    r.w = h2u(__floats2half2_rn(b.z, b.w));
    return r;
}

// smem tile geometry: rows x 16 half (32B), padded row stride 48 bytes
#define TROW 48
#define A_TB (128 * TROW)          /* 6144  */
#define B_TB (256 * TROW)          /* 12288 */
#define STAGE (A_TB + B_TB)        /* 18432 */
#define NSTAGE 6
#define GSMEM (NSTAGE * STAGE)     /* 110592 */
#define OAH 0
#define OBH A_TB

// ---------------- small kernels ---------------------------------------------
__global__ void init_k() {
    if (threadIdx.x < NE) g_counts[threadIdx.x] = 0;
}

__global__ void router_k(const float* __restrict__ x, const float* __restrict__ rW,
                         const int* __restrict__ elim_p, float* __restrict__ logits_out) {
    const int gwarp = (blockIdx.x * blockDim.x + threadIdx.x) >> 5;
    const int lane  = threadIdx.x & 31;
    if (gwarp >= NT) return;
    const float* xr = x + (size_t)gwarp * NH;
    float acc[NE];
#pragma unroll
    for (int e = 0; e < NE; ++e) acc[e] = 0.f;
    for (int h = lane; h < NH; h += 32) {
        const float xv = xr[h];
#pragma unroll
        for (int e = 0; e < NE; ++e) acc[e] = fmaf(xv, rW[e * NH + h], acc[e]);
    }
#pragma unroll
    for (int e = 0; e < NE; ++e)
#pragma unroll
        for (int o = 16; o > 0; o >>= 1) acc[e] += __shfl_xor_sync(0xffffffffu, acc[e], o);

    if (lane == 0) {
        const int elim = *elim_p;
#pragma unroll
        for (int e = 0; e < NE; ++e) if (e >= elim) acc[e] = -INFINITY;
#pragma unroll
        for (int e = 0; e < NE; ++e) logits_out[gwarp * NE + e] = acc[e];
        int i0 = 0; float v0 = acc[0];
        for (int e = 1; e < NE; ++e) if (acc[e] > v0) { v0 = acc[e]; i0 = e; }
        int i1 = -1; float v1 = -INFINITY;
        for (int e = 0; e < NE; ++e) { if (e == i0) continue; if (acc[e] > v1) { v1 = acc[e]; i1 = e; } }
        float w0, w1;
        if (i1 < 0) { i1 = (i0 + 1) & (NE - 1); w0 = 1.f; w1 = 0.f; }
        else {
            const float ex = expf(v1 - v0);
            w0 = 1.f / (1.f + ex);
            w1 = ex  / (1.f + ex);
        }
        g_top_i[gwarp * 2 + 0] = i0; g_top_i[gwarp * 2 + 1] = i1;
        g_top_w[gwarp * 2 + 0] = w0; g_top_w[gwarp * 2 + 1] = w1;
        atomicAdd(&g_counts[i0], 1);
        atomicAdd(&g_counts[i1], 1);
    }
}

__global__ void scan_k() {
    if (threadIdx.x == 0) {
        int o = 0;
        for (int e = 0; e < NE; ++e) { g_offsets[e] = o; o += g_counts[e]; g_cursor[e] = 0; }
    }
}

__global__ void scatter_k() {
    const int t = blockIdx.x * blockDim.x + threadIdx.x;
    if (t >= NT) return;
#pragma unroll
    for (int k = 0; k < 2; ++k) {
        const int e   = g_top_i[t * 2 + k];
        const int pos = g_offsets[e] + atomicAdd(&g_cursor[e], 1);
        g_pair_token[pos]       = t;
        g_token_pair[t * 2 + k] = pos;
    }
}

// ---------------- conversion kernels ----------------------------------------
// gate/up -> g_w1h interleaved: row = (e*(NF/8) + f/8)*16 + m*8 + (f&7)
__global__ void cvtw1_k(const float* __restrict__ gW, const float* __restrict__ uW) {
    const size_t idx = (size_t)blockIdx.x * blockDim.x + threadIdx.x;
    if (idx >= (size_t)NE * NF * (NH / 8)) return;
    const int hb  = idx % (NH / 8);
    const int f   = (idx / (NH / 8)) % NF;
    const int e   = idx / ((size_t)NF * (NH / 8));
    const size_t src = ((size_t)e * NF + f) * NH + hb * 8;
    const size_t rowg = ((size_t)e * (NF / 8) + (f >> 3)) * 16 + (f & 7);
    {
        float4 a = *(const float4*)(gW + src), b = *(const float4*)(gW + src + 4);
        *(uint4*)(g_w1h + rowg * NH + hb * 8) = cv8h(a, b);
    }
    {
        float4 a = *(const float4*)(uW + src), b = *(const float4*)(uW + src + 4);
        *(uint4*)(g_w1h + (rowg + 8) * NH + hb * 8) = cv8h(a, b);
    }
}

__global__ void cvtwd_k(const float* __restrict__ dW) {
    const size_t idx = (size_t)blockIdx.x * blockDim.x + threadIdx.x;
    if (idx >= (size_t)NE * NH * (NF / 8)) return;
    const size_t src = idx * 8;
    float4 a = *(const float4*)(dW + src), b = *(const float4*)(dW + src + 4);
    *(uint4*)(g_wdh + src) = cv8h(a, b);
}

__global__ void cvtx_k(const float* __restrict__ x) {
    const size_t idx = (size_t)blockIdx.x * blockDim.x + threadIdx.x;
    if (idx >= (size_t)NT * (NH / 8)) return;
    const size_t src = idx * 8;
    float4 a = *(const float4*)(x + src), b = *(const float4*)(x + src + 4);
    *(uint4*)(g_xh + src) = cv8h(a, b);
}

// ---------------- GEMM1: fp16 mma, cp.async 6-stage pipeline, BK=16 ----------
// CTA tile: 128 pairs x 128 F-cols (256 n-space, gate/up interleaved).
__global__ void __launch_bounds__(256)
gemm1_k() {
    const int e   = blockIdx.z;
    const int cnt = g_counts[e];
    const int m0  = blockIdx.x * 128;
    if (m0 >= cnt) return;
    const int off = g_offsets[e];
    const int f0  = blockIdx.y * 128;

    extern __shared__ char smem[];
    const uint32_t sb = s2u(smem);
    const int tid  = threadIdx.x;
    const int wid  = tid >> 5;
    const int lane = tid & 31;
    const int wm = wid >> 2, wn = wid & 3;

    // loader mapping: each thread copies 16B segments (row, half)
    const int lrow = tid >> 1;
    const int half = tid & 1;
    int mrow = m0 + lrow; if (mrow >= cnt) mrow = cnt - 1;
    const int tok = g_pair_token[off + mrow];
    const __half* axh = g_xh + (size_t)tok * NH + half * 8;
    const size_t bbase = ((size_t)e * (NF / 8) + (f0 >> 3)) * 16;
    const __half* bw0 = g_w1h + (bbase + lrow) * NH + half * 8;
    const __half* bw1 = g_w1h + (bbase + 128 + lrow) * NH + half * 8;
    const uint32_t a_soff  = lrow * TROW + half * 16;
    const uint32_t b_soff0 = lrow * TROW + half * 16;
    const uint32_t b_soff1 = (128 + lrow) * TROW + half * 16;

    float acc[4][8][4];
#pragma unroll
    for (int i = 0; i < 4; ++i)
#pragma unroll
        for (int j = 0; j < 8; ++j)
#pragma unroll
            for (int q = 0; q < 4; ++q) acc[i][j][q] = 0.f;

    const int NCH = NH / 16;   // 128
    // prologue: issue stages 0..4
#pragma unroll
    for (int s = 0; s < 5; ++s) {
        const uint32_t st = sb + s * STAGE;
        const int k = s * 16;
        cpa16(st + OAH + a_soff, axh + k);
        cpa16(st + OBH + b_soff0, bw0 + k);
        cpa16(st + OBH + b_soff1, bw1 + k);
        CPA_COMMIT();
    }

    const uint32_t afr = (wm * 64 + (lane & 15)) * TROW + (lane >> 4) * 16;
    const uint32_t bfr = (wn * 64 + ((lane >> 4) << 3) + (lane & 7)) * TROW + ((lane >> 3) & 1) * 16;

    int slot = 0, pslot = 5;
    for (int c = 0; c < NCH; ++c) {
        CPA_WAIT4();
        __syncthreads();

        // issue chunk c+5 into its slot (that slot's reads finished at iter c-1)
        if (c + 5 < NCH) {
            const uint32_t st = sb + pslot * STAGE;
            const int k = (c + 5) * 16;
            cpa16(st + OAH + a_soff, axh + k);
            cpa16(st + OBH + b_soff0, bw0 + k);
            cpa16(st + OBH + b_soff1, bw1 + k);
        }
        CPA_COMMIT();
        if (++pslot == NSTAGE) pslot = 0;

        const uint32_t st = sb + slot * STAGE;
        if (++slot == NSTAGE) slot = 0;
        uint32_t ah[4][4];
#pragma unroll
        for (int i = 0; i < 4; ++i)
            ldmx4(ah[i], st + OAH + afr + i * 16 * TROW);
#pragma unroll
        for (int jp = 0; jp < 4; ++jp) {
            uint32_t bh[4];
            ldmx4(bh, st + OBH + bfr + jp * 16 * TROW);
#pragma unroll
            for (int i = 0; i < 4; ++i) {
                mma16816(acc[i][2 * jp],     ah[i], bh[0], bh[1]);
                mma16816(acc[i][2 * jp + 1], ah[i], bh[2], bh[3]);
            }
        }
    }

    // epilogue: silu(gate)*up -> h1 as fp16
#pragma unroll
    for (int i = 0; i < 4; ++i) {
        const int r0l = wm * 64 + i * 16 + (lane >> 2);
        const int r1l = r0l + 8;
#pragma unroll
        for (int jp = 0; jp < 4; ++jp) {
            const int col = f0 + (wn * 4 + jp) * 8 + (lane & 3) * 2;
            const float* gv = acc[i][2 * jp];
            const float* uv = acc[i][2 * jp + 1];
            if (m0 + r0l < cnt) {
                float o0 = (gv[0] / (1.f + __expf(-gv[0]))) * uv[0];
                float o1 = (gv[1] / (1.f + __expf(-gv[1]))) * uv[1];
                const size_t p = (size_t)(off + m0 + r0l) * NF + col;
                *(uint32_t*)(g_h1h + p) = h2u(__floats2half2_rn(o0, o1));
            }
            if (m0 + r1l < cnt) {
                float o2 = (gv[2] / (1.f + __expf(-gv[2]))) * uv[2];
                float o3 = (gv[3] / (1.f + __expf(-gv[3]))) * uv[3];
                const size_t p = (size_t)(off + m0 + r1l) * NF + col;
                *(uint32_t*)(g_h1h + p) = h2u(__floats2half2_rn(o2, o3));
            }
        }
    }
}

// ---------------- GEMM2: fp16 mma, cp.async 6-stage pipeline, BK=16 ----------
// CTA tile: 128 pairs x 256 H-cols.
__global__ void __launch_bounds__(256)
gemm2_k(const float* __restrict__ db) {
    const int e   = blockIdx.z;
    const int cnt = g_counts[e];
    const int m0  = blockIdx.x * 128;
    if (m0 >= cnt) return;
    const int off = g_offsets[e];
    const int n0  = blockIdx.y * 256;

    extern __shared__ char smem[];
    const uint32_t sb = s2u(smem);
    const int tid  = threadIdx.x;
    const int wid  = tid >> 5;
    const int lane = tid & 31;
    const int wm = wid >> 2, wn = wid & 3;

    const int lrow = tid >> 1;
    const int half = tid & 1;
    int mrow = m0 + lrow; if (mrow >= cnt) mrow = cnt - 1;
    const __half* axh = g_h1h + (size_t)(off + mrow) * NF + half * 8;
    const __half* bw0 = g_wdh + ((size_t)e * NH + n0 + lrow) * NF + half * 8;
    const __half* bw1 = g_wdh + ((size_t)e * NH + n0 + 128 + lrow) * NF + half * 8;
    const uint32_t a_soff  = lrow * TROW + half * 16;
    const uint32_t b_soff0 = lrow * TROW + half * 16;
    const uint32_t b_soff1 = (128 + lrow) * TROW + half * 16;

    float acc[4][8][4];
#pragma unroll
    for (int i = 0; i < 4; ++i)
#pragma unroll
        for (int j = 0; j < 8; ++j)
#pragma unroll
            for (int q = 0; q < 4; ++q) acc[i][j][q] = 0.f;

    const int NCH = NF / 16;   // 352
#pragma unroll
    for (int s = 0; s < 5; ++s) {
        const uint32_t st = sb + s * STAGE;
        const int k = s * 16;
        cpa16(st + OAH + a_soff, axh + k);
        cpa16(st + OBH + b_soff0, bw0 + k);
        cpa16(st + OBH + b_soff1, bw1 + k);
        CPA_COMMIT();
    }

    const uint32_t afr = (wm * 64 + (lane & 15)) * TROW + (lane >> 4) * 16;
    const uint32_t bfr = (wn * 64 + ((lane >> 4) << 3) + (lane & 7)) * TROW + ((lane >> 3) & 1) * 16;

    int slot = 0, pslot = 5;
    for (int c = 0; c < NCH; ++c) {
        CPA_WAIT4();
        __syncthreads();

        if (c + 5 < NCH) {
            const uint32_t st = sb + pslot * STAGE;
            const int k = (c + 5) * 16;
            cpa16(st + OAH + a_soff, axh + k);
            cpa16(st + OBH + b_soff0, bw0 + k);
            cpa16(st + OBH + b_soff1, bw1 + k);
        }
        CPA_COMMIT();
        if (++pslot == NSTAGE) pslot = 0;

        const uint32_t st = sb + slot * STAGE;
        if (++slot == NSTAGE) slot = 0;
        uint32_t ah[4][4];
#pragma unroll
        for (int i = 0; i < 4; ++i)
            ldmx4(ah[i], st + OAH + afr + i * 16 * TROW);
#pragma unroll
        for (int jp = 0; jp < 4; ++jp) {
            uint32_t bh[4];
            ldmx4(bh, st + OBH + bfr + jp * 16 * TROW);
#pragma unroll
            for (int i = 0; i < 4; ++i) {
                mma16816(acc[i][2 * jp],     ah[i], bh[0], bh[1]);
                mma16816(acc[i][2 * jp + 1], ah[i], bh[2], bh[3]);
            }
        }
    }

#pragma unroll
    for (int i = 0; i < 4; ++i) {
        const int r0l = wm * 64 + i * 16 + (lane >> 2);
        const int r1l = r0l + 8;
#pragma unroll
        for (int j = 0; j < 8; ++j) {
            const int col = n0 + wn * 64 + j * 8 + (lane & 3) * 2;
            const float b0 = db[(size_t)e * NH + col];
            const float b1 = db[(size_t)e * NH + col + 1];
            if (m0 + r0l < cnt)
                *(uint32_t*)(g_hoh + (size_t)(off + m0 + r0l) * NH + col) =
                    h2u(__floats2half2_rn(acc[i][j][0] + b0, acc[i][j][1] + b1));
            if (m0 + r1l < cnt)
                *(uint32_t*)(g_hoh + (size_t)(off + m0 + r1l) * NH + col) =
                    h2u(__floats2half2_rn(acc[i][j][2] + b0, acc[i][j][3] + b1));
        }
    }
}

// ---------------- combine ----------------------------------------------------
__global__ void combine_k(const float* __restrict__ res, float* __restrict__ out) {
    const int idx = blockIdx.x * blockDim.x + threadIdx.x;
    const int NV  = NT * NH / 4;
    if (idx >= NV) return;
    const int t = idx >> 9;
    const int c = idx & 511;
    const int p0 = g_token_pair[2 * t + 0];
    const int p1 = g_token_pair[2 * t + 1];
    const float w0 = g_top_w[2 * t + 0];
    const float w1 = g_top_w[2 * t + 1];
    const float4 r = ((const float4*)res)[idx];
    const __half2* ap = (const __half2*)(g_hoh + (size_t)p0 * NH) + 2 * c;
    const __half2* bp = (const __half2*)(g_hoh + (size_t)p1 * NH) + 2 * c;
    float2 a0 = __half22float2(ap[0]), a1 = __half22float2(ap[1]);
    float2 b0 = __half22float2(bp[0]), b1 = __half22float2(bp[1]);
    float4 o;
    o.x = r.x + w0 * a0.x + w1 * b0.x;
    o.y = r.y + w0 * a0.y + w1 * b0.y;
    o.z = r.z + w0 * a1.x + w1 * b1.x;
    o.w = r.w + w0 * a1.y + w1 * b1.y;
    ((float4*)out)[idx] = o;
}

// ---------------- launch ----------------------------------------------------
extern "C" void kernel_launch(void* const* d_in, const int* in_sizes, int n_in,
                              void* d_out, int out_size) {
    const float* x    = (const float*)d_in[0];
    const float* res  = (const float*)d_in[1];
    const float* rW   = (const float*)d_in[2];
    const float* gW   = (const float*)d_in[3];
    const float* uW   = (const float*)d_in[4];
    const float* dW   = (const float*)d_in[5];
    const float* db   = (const float*)d_in[6];
    const int*   elim = (const int*)d_in[7];

    float* out    = (float*)d_out;
    float* logits = out + (size_t)NT * NH;

    cudaFuncSetAttribute(gemm1_k, cudaFuncAttributeMaxDynamicSharedMemorySize, GSMEM);
    cudaFuncSetAttribute(gemm2_k, cudaFuncAttributeMaxDynamicSharedMemorySize, GSMEM);

    init_k<<<1, 32>>>();
    router_k<<<NT / 8, 256>>>(x, rW, elim, logits);
    scan_k<<<1, 32>>>();
    scatter_k<<<NT / 256, 256>>>();

    const size_t nw1 = (size_t)NE * NF * (NH / 8);
    cvtw1_k<<<(unsigned)((nw1 + 255) / 256), 256>>>(gW, uW);
    const size_t nwd = (size_t)NE * NH * (NF / 8);
    cvtwd_k<<<(unsigned)((nwd + 255) / 256), 256>>>(dW);
    const size_t nx = (size_t)NT * (NH / 8);
    cvtx_k<<<(unsigned)((nx + 255) / 256), 256>>>(x);

    gemm1_k<<<dim3(NT / 128, NF / 128, NE), 256, GSMEM>>>();
    gemm2_k<<<dim3(NT / 128, NH / 256, NE), 256, GSMEM>>>(db);
    combine_k<<<(NT * NH / 4 + 255) / 256, 256>>>(res, out);
}

// round 14
// speedup vs baseline: 1.1785x; 1.1398x over previous
#include <cuda_runtime.h>
#include <cuda_fp16.h>
#include <math.h>
#include <stdint.h>

#define NB 4
#define NS 2048
#define NH 2048
#define NF 5632
#define NE 8
#define NT (NB * NS)   /* 8192 tokens */
#define NP (NT * 2)    /* 16384 (token, expert) pairs */

// ---------------- scratch (device globals) ----------------------------------
__device__ __half g_h1h[(size_t)NP * NF];
__device__ __half g_hoh[(size_t)NP * NH];
__device__ __half g_xh[(size_t)NT * NH];
// gemm1 B: per expert, NF/8 blocks x {gate,up} x 8 rows, each row NH halfs
__device__ __half g_w1h[(size_t)NE * NF * 2 * NH];
__device__ __half g_wdh[(size_t)NE * NH * NF];
__device__ int   g_top_i[NP];
__device__ float g_top_w[NP];
__device__ int   g_pair_token[NP];
__device__ int   g_token_pair[NP];
__device__ int   g_counts[NE];
__device__ int   g_offsets[NE];
__device__ int   g_cursor[NE];

// ---------------- helpers ----------------------------------------------------
__device__ __forceinline__ uint32_t s2u(const void* p) {
    uint32_t a;
    asm("{ .reg .u64 t; cvta.to.shared.u64 t, %1; cvt.u32.u64 %0, t; }" : "=r"(a) : "l"(p));
    return a;
}
__device__ __forceinline__ void ldmx4(uint32_t* r, uint32_t a) {
    asm volatile("ldmatrix.sync.aligned.m8n8.x4.shared.b16 {%0,%1,%2,%3}, [%4];"
                 : "=r"(r[0]), "=r"(r[1]), "=r"(r[2]), "=r"(r[3]) : "r"(a));
}
__device__ __forceinline__ void mma16816(float* c, const uint32_t* a, uint32_t b0, uint32_t b1) {
    asm volatile(
        "mma.sync.aligned.m16n8k16.row.col.f32.f16.f16.f32 "
        "{%0,%1,%2,%3}, {%4,%5,%6,%7}, {%8,%9}, {%0,%1,%2,%3};"
        : "+f"(c[0]), "+f"(c[1]), "+f"(c[2]), "+f"(c[3])
        : "r"(a[0]), "r"(a[1]), "r"(a[2]), "r"(a[3]), "r"(b0), "r"(b1));
}
__device__ __forceinline__ uint32_t h2u(__half2 v) { return *reinterpret_cast<uint32_t*>(&v); }

__device__ __forceinline__ void cpa16(uint32_t dst, const void* src) {
    asm volatile("cp.async.cg.shared.global [%0], [%1], 16;" :: "r"(dst), "l"(src));
}
#define CPA_COMMIT() asm volatile("cp.async.commit_group;" ::: "memory")
#define CPA_WAIT2()  asm volatile("cp.async.wait_group 2;" ::: "memory")

// convert 8 fp32 -> 8 fp16 (uint4)
__device__ __forceinline__ uint4 cv8h(float4 a, float4 b) {
    uint4 r;
    r.x = h2u(__floats2half2_rn(a.x, a.y));
    r.y = h2u(__floats2half2_rn(a.z, a.w));
    r.z = h2u(__floats2half2_rn(b.x, b.y));
    r.w = h2u(__floats2half2_rn(b.z, b.w));
    return r;
}

// smem tile geometry: rows x 16 half (32B), padded row stride 48 bytes
#define TROW 48
#define A_TB (128 * TROW)          /* 6144  */
#define B_TB (256 * TROW)          /* 12288 */
#define STAGE (A_TB + B_TB)        /* 18432 */
#define NSTAGE 4
#define GSMEM (NSTAGE * STAGE)     /* 73728 */
#define OAH 0
#define OBH A_TB

// ---------------- small kernels ---------------------------------------------
__global__ void init_k() {
    if (threadIdx.x < NE) g_counts[threadIdx.x] = 0;
}

__global__ void router_k(const float* __restrict__ x, const float* __restrict__ rW,
                         const int* __restrict__ elim_p, float* __restrict__ logits_out) {
    const int gwarp = (blockIdx.x * blockDim.x + threadIdx.x) >> 5;
    const int lane  = threadIdx.x & 31;
    if (gwarp >= NT) return;
    const float* xr = x + (size_t)gwarp * NH;
    float acc[NE];
#pragma unroll
    for (int e = 0; e < NE; ++e) acc[e] = 0.f;
    for (int h = lane; h < NH; h += 32) {
        const float xv = xr[h];
#pragma unroll
        for (int e = 0; e < NE; ++e) acc[e] = fmaf(xv, rW[e * NH + h], acc[e]);
    }
#pragma unroll
    for (int e = 0; e < NE; ++e)
#pragma unroll
        for (int o = 16; o > 0; o >>= 1) acc[e] += __shfl_xor_sync(0xffffffffu, acc[e], o);

    if (lane == 0) {
        const int elim = *elim_p;
#pragma unroll
        for (int e = 0; e < NE; ++e) if (e >= elim) acc[e] = -INFINITY;
#pragma unroll
        for (int e = 0; e < NE; ++e) logits_out[gwarp * NE + e] = acc[e];
        int i0 = 0; float v0 = acc[0];
        for (int e = 1; e < NE; ++e) if (acc[e] > v0) { v0 = acc[e]; i0 = e; }
        int i1 = -1; float v1 = -INFINITY;
        for (int e = 0; e < NE; ++e) { if (e == i0) continue; if (acc[e] > v1) { v1 = acc[e]; i1 = e; } }
        float w0, w1;
        if (i1 < 0) { i1 = (i0 + 1) & (NE - 1); w0 = 1.f; w1 = 0.f; }
        else {
            const float ex = expf(v1 - v0);
            w0 = 1.f / (1.f + ex);
            w1 = ex  / (1.f + ex);
        }
        g_top_i[gwarp * 2 + 0] = i0; g_top_i[gwarp * 2 + 1] = i1;
        g_top_w[gwarp * 2 + 0] = w0; g_top_w[gwarp * 2 + 1] = w1;
        atomicAdd(&g_counts[i0], 1);
        atomicAdd(&g_counts[i1], 1);
    }
}

__global__ void scan_k() {
    if (threadIdx.x == 0) {
        int o = 0;
        for (int e = 0; e < NE; ++e) { g_offsets[e] = o; o += g_counts[e]; g_cursor[e] = 0; }
    }
}

__global__ void scatter_k() {
    const int t = blockIdx.x * blockDim.x + threadIdx.x;
    if (t >= NT) return;
#pragma unroll
    for (int k = 0; k < 2; ++k) {
        const int e   = g_top_i[t * 2 + k];
        const int pos = g_offsets[e] + atomicAdd(&g_cursor[e], 1);
        g_pair_token[pos]       = t;
        g_token_pair[t * 2 + k] = pos;
    }
}

// ---------------- conversion kernels ----------------------------------------
// gate/up -> g_w1h interleaved: row = (e*(NF/8) + f/8)*16 + m*8 + (f&7)
__global__ void cvtw1_k(const float* __restrict__ gW, const float* __restrict__ uW) {
    const size_t idx = (size_t)blockIdx.x * blockDim.x + threadIdx.x;
    if (idx >= (size_t)NE * NF * (NH / 8)) return;
    const int hb  = idx % (NH / 8);
    const int f   = (idx / (NH / 8)) % NF;
    const int e   = idx / ((size_t)NF * (NH / 8));
    const size_t src = ((size_t)e * NF + f) * NH + hb * 8;
    const size_t rowg = ((size_t)e * (NF / 8) + (f >> 3)) * 16 + (f & 7);
    {
        float4 a = *(const float4*)(gW + src), b = *(const float4*)(gW + src + 4);
        *(uint4*)(g_w1h + rowg * NH + hb * 8) = cv8h(a, b);
    }
    {
        float4 a = *(const float4*)(uW + src), b = *(const float4*)(uW + src + 4);
        *(uint4*)(g_w1h + (rowg + 8) * NH + hb * 8) = cv8h(a, b);
    }
}

__global__ void cvtwd_k(const float* __restrict__ dW) {
    const size_t idx = (size_t)blockIdx.x * blockDim.x + threadIdx.x;
    if (idx >= (size_t)NE * NH * (NF / 8)) return;
    const size_t src = idx * 8;
    float4 a = *(const float4*)(dW + src), b = *(const float4*)(dW + src + 4);
    *(uint4*)(g_wdh + src) = cv8h(a, b);
}

__global__ void cvtx_k(const float* __restrict__ x) {
    const size_t idx = (size_t)blockIdx.x * blockDim.x + threadIdx.x;
    if (idx >= (size_t)NT * (NH / 8)) return;
    const size_t src = idx * 8;
    float4 a = *(const float4*)(x + src), b = *(const float4*)(x + src + 4);
    *(uint4*)(g_xh + src) = cv8h(a, b);
}

// ---------------- GEMM1: fp16 mma, cp.async 4-stage pipeline, BK=16 ----------
// CTA tile: 128 pairs x 128 F-cols (256 n-space, gate/up interleaved).
__global__ void __launch_bounds__(256)
gemm1_k() {
    const int e   = blockIdx.z;
    const int cnt = g_counts[e];
    const int m0  = blockIdx.x * 128;
    if (m0 >= cnt) return;
    const int off = g_offsets[e];
    const int f0  = blockIdx.y * 128;

    extern __shared__ char smem[];
    const uint32_t sb = s2u(smem);
    const int tid  = threadIdx.x;
    const int wid  = tid >> 5;
    const int lane = tid & 31;
    const int wm = wid >> 2, wn = wid & 3;

    // loader mapping: each thread copies 16B segments (row, half)
    const int lrow = tid >> 1;
    const int half = tid & 1;
    int mrow = m0 + lrow; if (mrow >= cnt) mrow = cnt - 1;
    const int tok = g_pair_token[off + mrow];
    const __half* axh = g_xh + (size_t)tok * NH + half * 8;
    const size_t bbase = ((size_t)e * (NF / 8) + (f0 >> 3)) * 16;
    const __half* bw0 = g_w1h + (bbase + lrow) * NH + half * 8;
    const __half* bw1 = g_w1h + (bbase + 128 + lrow) * NH + half * 8;
    const uint32_t a_soff  = lrow * TROW + half * 16;
    const uint32_t b_soff0 = lrow * TROW + half * 16;
    const uint32_t b_soff1 = (128 + lrow) * TROW + half * 16;

    float acc[4][8][4];
#pragma unroll
    for (int i = 0; i < 4; ++i)
#pragma unroll
        for (int j = 0; j < 8; ++j)
#pragma unroll
            for (int q = 0; q < 4; ++q) acc[i][j][q] = 0.f;

    const int NCH = NH / 16;   // 128
    // prologue: issue stages 0..2
#pragma unroll
    for (int s = 0; s < 3; ++s) {
        const uint32_t st = sb + s * STAGE;
        const int k = s * 16;
        cpa16(st + OAH + a_soff, axh + k);
        cpa16(st + OBH + b_soff0, bw0 + k);
        cpa16(st + OBH + b_soff1, bw1 + k);
        CPA_COMMIT();
    }

    const uint32_t afr = (wm * 64 + (lane & 15)) * TROW + (lane >> 4) * 16;
    const uint32_t bfr = (wn * 64 + ((lane >> 4) << 3) + (lane & 7)) * TROW + ((lane >> 3) & 1) * 16;

    for (int c = 0; c < NCH; ++c) {
        CPA_WAIT2();
        __syncthreads();

        // issue chunk c+3 into slot (c+3)%4 (that slot's reads finished at iter c-1)
        if (c + 3 < NCH) {
            const uint32_t st = sb + ((c + 3) & 3) * STAGE;
            const int k = (c + 3) * 16;
            cpa16(st + OAH + a_soff, axh + k);
            cpa16(st + OBH + b_soff0, bw0 + k);
            cpa16(st + OBH + b_soff1, bw1 + k);
        }
        CPA_COMMIT();

        const uint32_t st = sb + (c & 3) * STAGE;
        uint32_t ah[4][4];
#pragma unroll
        for (int i = 0; i < 4; ++i)
            ldmx4(ah[i], st + OAH + afr + i * 16 * TROW);
#pragma unroll
        for (int jp = 0; jp < 4; ++jp) {
            uint32_t bh[4];
            ldmx4(bh, st + OBH + bfr + jp * 16 * TROW);
#pragma unroll
            for (int i = 0; i < 4; ++i) {
                mma16816(acc[i][2 * jp],     ah[i], bh[0], bh[1]);
                mma16816(acc[i][2 * jp + 1], ah[i], bh[2], bh[3]);
            }
        }
    }

    // epilogue: silu(gate)*up -> h1 as fp16
#pragma unroll
    for (int i = 0; i < 4; ++i) {
        const int r0l = wm * 64 + i * 16 + (lane >> 2);
        const int r1l = r0l + 8;
#pragma unroll
        for (int jp = 0; jp < 4; ++jp) {
            const int col = f0 + (wn * 4 + jp) * 8 + (lane & 3) * 2;
            const float* gv = acc[i][2 * jp];
            const float* uv = acc[i][2 * jp + 1];
            if (m0 + r0l < cnt) {
                float o0 = (gv[0] / (1.f + __expf(-gv[0]))) * uv[0];
                float o1 = (gv[1] / (1.f + __expf(-gv[1]))) * uv[1];
                const size_t p = (size_t)(off + m0 + r0l) * NF + col;
                *(uint32_t*)(g_h1h + p) = h2u(__floats2half2_rn(o0, o1));
            }
            if (m0 + r1l < cnt) {
                float o2 = (gv[2] / (1.f + __expf(-gv[2]))) * uv[2];
                float o3 = (gv[3] / (1.f + __expf(-gv[3]))) * uv[3];
                const size_t p = (size_t)(off + m0 + r1l) * NF + col;
                *(uint32_t*)(g_h1h + p) = h2u(__floats2half2_rn(o2, o3));
            }
        }
    }
}

// ---------------- GEMM2: fp16 mma, cp.async 4-stage pipeline, BK=16 ----------
// CTA tile: 128 pairs x 256 H-cols.
__global__ void __launch_bounds__(256)
gemm2_k(const float* __restrict__ db) {
    const int e   = blockIdx.z;
    const int cnt = g_counts[e];
    const int m0  = blockIdx.x * 128;
    if (m0 >= cnt) return;
    const int off = g_offsets[e];
    const int n0  = blockIdx.y * 256;

    extern __shared__ char smem[];
    const uint32_t sb = s2u(smem);
    const int tid  = threadIdx.x;
    const int wid  = tid >> 5;
    const int lane = tid & 31;
    const int wm = wid >> 2, wn = wid & 3;

    const int lrow = tid >> 1;
    const int half = tid & 1;
    int mrow = m0 + lrow; if (mrow >= cnt) mrow = cnt - 1;
    const __half* axh = g_h1h + (size_t)(off + mrow) * NF + half * 8;
    const __half* bw0 = g_wdh + ((size_t)e * NH + n0 + lrow) * NF + half * 8;
    const __half* bw1 = g_wdh + ((size_t)e * NH + n0 + 128 + lrow) * NF + half * 8;
    const uint32_t a_soff  = lrow * TROW + half * 16;
    const uint32_t b_soff0 = lrow * TROW + half * 16;
    const uint32_t b_soff1 = (128 + lrow) * TROW + half * 16;

    float acc[4][8][4];
#pragma unroll
    for (int i = 0; i < 4; ++i)
#pragma unroll
        for (int j = 0; j < 8; ++j)
#pragma unroll
            for (int q = 0; q < 4; ++q) acc[i][j][q] = 0.f;

    const int NCH = NF / 16;   // 352
#pragma unroll
    for (int s = 0; s < 3; ++s) {
        const uint32_t st = sb + s * STAGE;
        const int k = s * 16;
        cpa16(st + OAH + a_soff, axh + k);
        cpa16(st + OBH + b_soff0, bw0 + k);
        cpa16(st + OBH + b_soff1, bw1 + k);
        CPA_COMMIT();
    }

    const uint32_t afr = (wm * 64 + (lane & 15)) * TROW + (lane >> 4) * 16;
    const uint32_t bfr = (wn * 64 + ((lane >> 4) << 3) + (lane & 7)) * TROW + ((lane >> 3) & 1) * 16;

    for (int c = 0; c < NCH; ++c) {
        CPA_WAIT2();
        __syncthreads();

        if (c + 3 < NCH) {
            const uint32_t st = sb + ((c + 3) & 3) * STAGE;
            const int k = (c + 3) * 16;
            cpa16(st + OAH + a_soff, axh + k);
            cpa16(st + OBH + b_soff0, bw0 + k);
            cpa16(st + OBH + b_soff1, bw1 + k);
        }
        CPA_COMMIT();

        const uint32_t st = sb + (c & 3) * STAGE;
        uint32_t ah[4][4];
#pragma unroll
        for (int i = 0; i < 4; ++i)
            ldmx4(ah[i], st + OAH + afr + i * 16 * TROW);
#pragma unroll
        for (int jp = 0; jp < 4; ++jp) {
            uint32_t bh[4];
            ldmx4(bh, st + OBH + bfr + jp * 16 * TROW);
#pragma unroll
            for (int i = 0; i < 4; ++i) {
                mma16816(acc[i][2 * jp],     ah[i], bh[0], bh[1]);
                mma16816(acc[i][2 * jp + 1], ah[i], bh[2], bh[3]);
            }
        }
    }

#pragma unroll
    for (int i = 0; i < 4; ++i) {
        const int r0l = wm * 64 + i * 16 + (lane >> 2);
        const int r1l = r0l + 8;
#pragma unroll
        for (int j = 0; j < 8; ++j) {
            const int col = n0 + wn * 64 + j * 8 + (lane & 3) * 2;
            const float b0 = db[(size_t)e * NH + col];
            const float b1 = db[(size_t)e * NH + col + 1];
            if (m0 + r0l < cnt)
                *(uint32_t*)(g_hoh + (size_t)(off + m0 + r0l) * NH + col) =
                    h2u(__floats2half2_rn(acc[i][j][0] + b0, acc[i][j][1] + b1));
            if (m0 + r1l < cnt)
                *(uint32_t*)(g_hoh + (size_t)(off + m0 + r1l) * NH + col) =
                    h2u(__floats2half2_rn(acc[i][j][2] + b0, acc[i][j][3] + b1));
        }
    }
}

// ---------------- combine ----------------------------------------------------
__global__ void combine_k(const float* __restrict__ res, float* __restrict__ out) {
    const int idx = blockIdx.x * blockDim.x + threadIdx.x;
    const int NV  = NT * NH / 4;
    if (idx >= NV) return;
    const int t = idx >> 9;
    const int c = idx & 511;
    const int p0 = g_token_pair[2 * t + 0];
    const int p1 = g_token_pair[2 * t + 1];
    const float w0 = g_top_w[2 * t + 0];
    const float w1 = g_top_w[2 * t + 1];
    const float4 r = ((const float4*)res)[idx];
    const __half2* ap = (const __half2*)(g_hoh + (size_t)p0 * NH) + 2 * c;
    const __half2* bp = (const __half2*)(g_hoh + (size_t)p1 * NH) + 2 * c;
    float2 a0 = __half22float2(ap[0]), a1 = __half22float2(ap[1]);
    float2 b0 = __half22float2(bp[0]), b1 = __half22float2(bp[1]);
    float4 o;
    o.x = r.x + w0 * a0.x + w1 * b0.x;
    o.y = r.y + w0 * a0.y + w1 * b0.y;
    o.z = r.z + w0 * a1.x + w1 * b1.x;
    o.w = r.w + w0 * a1.y + w1 * b1.y;
    ((float4*)out)[idx] = o;
}

// ---------------- launch ----------------------------------------------------
extern "C" void kernel_launch(void* const* d_in, const int* in_sizes, int n_in,
                              void* d_out, int out_size) {
    const float* x    = (const float*)d_in[0];
    const float* res  = (const float*)d_in[1];
    const float* rW   = (const float*)d_in[2];
    const float* gW   = (const float*)d_in[3];
    const float* uW   = (const float*)d_in[4];
    const float* dW   = (const float*)d_in[5];
    const float* db   = (const float*)d_in[6];
    const int*   elim = (const int*)d_in[7];

    float* out    = (float*)d_out;
    float* logits = out + (size_t)NT * NH;

    cudaFuncSetAttribute(gemm1_k, cudaFuncAttributeMaxDynamicSharedMemorySize, GSMEM);
    cudaFuncSetAttribute(gemm2_k, cudaFuncAttributeMaxDynamicSharedMemorySize, GSMEM);

    init_k<<<1, 32>>>();
    router_k<<<NT / 8, 256>>>(x, rW, elim, logits);
    scan_k<<<1, 32>>>();
    scatter_k<<<NT / 256, 256>>>();

    const size_t nw1 = (size_t)NE * NF * (NH / 8);
    cvtw1_k<<<(unsigned)((nw1 + 255) / 256), 256>>>(gW, uW);
    const size_t nwd = (size_t)NE * NH * (NF / 8);
    cvtwd_k<<<(unsigned)((nwd + 255) / 256), 256>>>(dW);
    const size_t nx = (size_t)NT * (NH / 8);
    cvtx_k<<<(unsigned)((nx + 255) / 256), 256>>>(x);

    gemm1_k<<<dim3(NT / 128, NF / 128, NE), 256, GSMEM>>>();
    gemm2_k<<<dim3(NT / 128, NH / 256, NE), 256, GSMEM>>>(db);
    combine_k<<<(NT * NH / 4 + 255) / 256, 256>>>(res, out);
}

// round 15
// speedup vs baseline: 1.2881x; 1.0930x over previous
#include <cuda_runtime.h>
#include <cuda_fp16.h>
#include <math.h>
#include <stdint.h>

#define NB 4
#define NS 2048
#define NH 2048
#define NF 5632
#define NE 8
#define NT (NB * NS)   /* 8192 tokens */
#define NP (NT * 2)    /* 16384 (token, expert) pairs */

// ---------------- scratch (device globals) ----------------------------------
__device__ __half g_h1h[(size_t)NP * NF];
__device__ __half g_hoh[(size_t)NP * NH];
__device__ __half g_xh[(size_t)NT * NH];
// gemm1 B: per expert, NF/8 blocks x {gate,up} x 8 rows, each row NH halfs
__device__ __half g_w1h[(size_t)NE * NF * 2 * NH];
__device__ __half g_wdh[(size_t)NE * NH * NF];
__device__ int   g_top_i[NP];
__device__ float g_top_w[NP];
__device__ int   g_pair_token[NP];
__device__ int   g_token_pair[NP];
__device__ int   g_counts[NE];
__device__ int   g_offsets[NE];
__device__ int   g_cursor[NE];

// ---------------- helpers ----------------------------------------------------
__device__ __forceinline__ uint32_t s2u(const void* p) {
    uint32_t a;
    asm("{ .reg .u64 t; cvta.to.shared.u64 t, %1; cvt.u32.u64 %0, t; }" : "=r"(a) : "l"(p));
    return a;
}
__device__ __forceinline__ void ldmx4(uint32_t* r, uint32_t a) {
    asm volatile("ldmatrix.sync.aligned.m8n8.x4.shared.b16 {%0,%1,%2,%3}, [%4];"
                 : "=r"(r[0]), "=r"(r[1]), "=r"(r[2]), "=r"(r[3]) : "r"(a));
}
__device__ __forceinline__ void mma16816(float* c, const uint32_t* a, uint32_t b0, uint32_t b1) {
    asm volatile(
        "mma.sync.aligned.m16n8k16.row.col.f32.f16.f16.f32 "
        "{%0,%1,%2,%3}, {%4,%5,%6,%7}, {%8,%9}, {%0,%1,%2,%3};"
        : "+f"(c[0]), "+f"(c[1]), "+f"(c[2]), "+f"(c[3])
        : "r"(a[0]), "r"(a[1]), "r"(a[2]), "r"(a[3]), "r"(b0), "r"(b1));
}
__device__ __forceinline__ uint32_t h2u(__half2 v) { return *reinterpret_cast<uint32_t*>(&v); }

__device__ __forceinline__ void cpa16(uint32_t dst, const void* src) {
    asm volatile("cp.async.cg.shared.global [%0], [%1], 16;" :: "r"(dst), "l"(src));
}
#define CPA_COMMIT() asm volatile("cp.async.commit_group;" ::: "memory")
#define CPA_WAIT2()  asm volatile("cp.async.wait_group 2;" ::: "memory")
#define CPA_WAIT1()  asm volatile("cp.async.wait_group 1;" ::: "memory")

// convert 8 fp32 -> 8 fp16 (uint4)
__device__ __forceinline__ uint4 cv8h(float4 a, float4 b) {
    uint4 r;
    r.x = h2u(__floats2half2_rn(a.x, a.y));
    r.y = h2u(__floats2half2_rn(a.z, a.w));
    r.z = h2u(__floats2half2_rn(b.x, b.y));
    r.w = h2u(__floats2half2_rn(b.z, b.w));
    return r;
}

// smem tile geometry: rows x 16 half (32B), padded row stride 48 bytes
#define TROW 48
#define A_TB (128 * TROW)          /* 6144  */
#define B_TB (256 * TROW)          /* 12288 */
#define STAGE (A_TB + B_TB)        /* 18432 */
#define NSTAGE 4
#define GSMEM (NSTAGE * STAGE)     /* 73728 */
#define OAH 0
#define OBH A_TB

// ---------------- small kernels ---------------------------------------------
__global__ void init_k() {
    if (threadIdx.x < NE) g_counts[threadIdx.x] = 0;
}

__global__ void router_k(const float* __restrict__ x, const float* __restrict__ rW,
                         const int* __restrict__ elim_p, float* __restrict__ logits_out) {
    const int gwarp = (blockIdx.x * blockDim.x + threadIdx.x) >> 5;
    const int lane  = threadIdx.x & 31;
    if (gwarp >= NT) return;
    const float* xr = x + (size_t)gwarp * NH;
    float acc[NE];
#pragma unroll
    for (int e = 0; e < NE; ++e) acc[e] = 0.f;
    for (int h = lane; h < NH; h += 32) {
        const float xv = xr[h];
#pragma unroll
        for (int e = 0; e < NE; ++e) acc[e] = fmaf(xv, rW[e * NH + h], acc[e]);
    }
#pragma unroll
    for (int e = 0; e < NE; ++e)
#pragma unroll
        for (int o = 16; o > 0; o >>= 1) acc[e] += __shfl_xor_sync(0xffffffffu, acc[e], o);

    if (lane == 0) {
        const int elim = *elim_p;
#pragma unroll
        for (int e = 0; e < NE; ++e) if (e >= elim) acc[e] = -INFINITY;
#pragma unroll
        for (int e = 0; e < NE; ++e) logits_out[gwarp * NE + e] = acc[e];
        int i0 = 0; float v0 = acc[0];
        for (int e = 1; e < NE; ++e) if (acc[e] > v0) { v0 = acc[e]; i0 = e; }
        int i1 = -1; float v1 = -INFINITY;
        for (int e = 0; e < NE; ++e) { if (e == i0) continue; if (acc[e] > v1) { v1 = acc[e]; i1 = e; } }
        float w0, w1;
        if (i1 < 0) { i1 = (i0 + 1) & (NE - 1); w0 = 1.f; w1 = 0.f; }
        else {
            const float ex = expf(v1 - v0);
            w0 = 1.f / (1.f + ex);
            w1 = ex  / (1.f + ex);
        }
        g_top_i[gwarp * 2 + 0] = i0; g_top_i[gwarp * 2 + 1] = i1;
        g_top_w[gwarp * 2 + 0] = w0; g_top_w[gwarp * 2 + 1] = w1;
        atomicAdd(&g_counts[i0], 1);
        atomicAdd(&g_counts[i1], 1);
    }
}

__global__ void scan_k() {
    if (threadIdx.x == 0) {
        int o = 0;
        for (int e = 0; e < NE; ++e) { g_offsets[e] = o; o += g_counts[e]; g_cursor[e] = 0; }
    }
}

__global__ void scatter_k() {
    const int t = blockIdx.x * blockDim.x + threadIdx.x;
    if (t >= NT) return;
#pragma unroll
    for (int k = 0; k < 2; ++k) {
        const int e   = g_top_i[t * 2 + k];
        const int pos = g_offsets[e] + atomicAdd(&g_cursor[e], 1);
        g_pair_token[pos]       = t;
        g_token_pair[t * 2 + k] = pos;
    }
}

// ---------------- conversion kernels ----------------------------------------
// gate/up -> g_w1h interleaved: row = (e*(NF/8) + f/8)*16 + m*8 + (f&7)
__global__ void cvtw1_k(const float* __restrict__ gW, const float* __restrict__ uW) {
    const size_t idx = (size_t)blockIdx.x * blockDim.x + threadIdx.x;
    if (idx >= (size_t)NE * NF * (NH / 8)) return;
    const int hb  = idx % (NH / 8);
    const int f   = (idx / (NH / 8)) % NF;
    const int e   = idx / ((size_t)NF * (NH / 8));
    const size_t src = ((size_t)e * NF + f) * NH + hb * 8;
    const size_t rowg = ((size_t)e * (NF / 8) + (f >> 3)) * 16 + (f & 7);
    {
        float4 a = *(const float4*)(gW + src), b = *(const float4*)(gW + src + 4);
        *(uint4*)(g_w1h + rowg * NH + hb * 8) = cv8h(a, b);
    }
    {
        float4 a = *(const float4*)(uW + src), b = *(const float4*)(uW + src + 4);
        *(uint4*)(g_w1h + (rowg + 8) * NH + hb * 8) = cv8h(a, b);
    }
}

__global__ void cvtwd_k(const float* __restrict__ dW) {
    const size_t idx = (size_t)blockIdx.x * blockDim.x + threadIdx.x;
    if (idx >= (size_t)NE * NH * (NF / 8)) return;
    const size_t src = idx * 8;
    float4 a = *(const float4*)(dW + src), b = *(const float4*)(dW + src + 4);
    *(uint4*)(g_wdh + src) = cv8h(a, b);
}

__global__ void cvtx_k(const float* __restrict__ x) {
    const size_t idx = (size_t)blockIdx.x * blockDim.x + threadIdx.x;
    if (idx >= (size_t)NT * (NH / 8)) return;
    const size_t src = idx * 8;
    float4 a = *(const float4*)(x + src), b = *(const float4*)(x + src + 4);
    *(uint4*)(g_xh + src) = cv8h(a, b);
}

// ---------------- GEMM1: fp16 mma, cp.async + register double-buffer --------
// CTA tile: 128 pairs x 128 F-cols (256 n-space, gate/up interleaved).
__global__ void __launch_bounds__(256)
gemm1_k() {
    const int e   = blockIdx.z;
    const int cnt = g_counts[e];
    const int m0  = blockIdx.x * 128;
    if (m0 >= cnt) return;
    const int off = g_offsets[e];
    const int f0  = blockIdx.y * 128;

    extern __shared__ char smem[];
    const uint32_t sb = s2u(smem);
    const int tid  = threadIdx.x;
    const int wid  = tid >> 5;
    const int lane = tid & 31;
    const int wm = wid >> 2, wn = wid & 3;

    // loader mapping: each thread copies 16B segments (row, half)
    const int lrow = tid >> 1;
    const int half = tid & 1;
    int mrow = m0 + lrow; if (mrow >= cnt) mrow = cnt - 1;
    const int tok = g_pair_token[off + mrow];
    const __half* axh = g_xh + (size_t)tok * NH + half * 8;
    const size_t bbase = ((size_t)e * (NF / 8) + (f0 >> 3)) * 16;
    const __half* bw0 = g_w1h + (bbase + lrow) * NH + half * 8;
    const __half* bw1 = g_w1h + (bbase + 128 + lrow) * NH + half * 8;
    const uint32_t a_soff  = lrow * TROW + half * 16;
    const uint32_t b_soff0 = lrow * TROW + half * 16;
    const uint32_t b_soff1 = (128 + lrow) * TROW + half * 16;

    float acc[4][8][4];
#pragma unroll
    for (int i = 0; i < 4; ++i)
#pragma unroll
        for (int j = 0; j < 8; ++j)
#pragma unroll
            for (int q = 0; q < 4; ++q) acc[i][j][q] = 0.f;

    const int NCH = NH / 16;   // 128
    // prologue: issue stages 0..2
#pragma unroll
    for (int s = 0; s < 3; ++s) {
        const uint32_t st = sb + s * STAGE;
        const int k = s * 16;
        cpa16(st + OAH + a_soff, axh + k);
        cpa16(st + OBH + b_soff0, bw0 + k);
        cpa16(st + OBH + b_soff1, bw1 + k);
        CPA_COMMIT();
    }

    const uint32_t afr = (wm * 64 + (lane & 15)) * TROW + (lane >> 4) * 16;
    const uint32_t bfr = (wn * 64 + ((lane >> 4) << 3) + (lane & 7)) * TROW + ((lane >> 3) & 1) * 16;

    // register fragment double-buffer: load chunk 0 fragments
    uint32_t ah[2][4][4], bh[2][4][4];
    CPA_WAIT2();         // group 0 complete (3 committed, wait <=2)
    __syncthreads();
#pragma unroll
    for (int i = 0; i < 4; ++i) ldmx4(ah[0][i], sb + OAH + afr + i * 16 * TROW);
#pragma unroll
    for (int jp = 0; jp < 4; ++jp) ldmx4(bh[0][jp], sb + OBH + bfr + jp * 16 * TROW);

    for (int c = 0; c < NCH; ++c) {
        const int p = c & 1;
        CPA_WAIT1();      // group c+1 complete
        __syncthreads();

        // issue chunk c+3 into slot (c+3)%4 (that slot's reads finished at iter c-1)
        if (c + 3 < NCH) {
            const uint32_t st = sb + ((c + 3) & 3) * STAGE;
            const int k = (c + 3) * 16;
            cpa16(st + OAH + a_soff, axh + k);
            cpa16(st + OBH + b_soff0, bw0 + k);
            cpa16(st + OBH + b_soff1, bw1 + k);
        }
        CPA_COMMIT();

        // prefetch fragments for chunk c+1 (slot (c+1)&3; data ready via WAIT1)
        if (c + 1 < NCH) {
            const uint32_t st = sb + ((c + 1) & 3) * STAGE;
#pragma unroll
            for (int i = 0; i < 4; ++i) ldmx4(ah[1 - p][i], st + OAH + afr + i * 16 * TROW);
#pragma unroll
            for (int jp = 0; jp < 4; ++jp) ldmx4(bh[1 - p][jp], st + OBH + bfr + jp * 16 * TROW);
        }

        // compute chunk c from resident fragments (overlaps the LDSM above)
#pragma unroll
        for (int jp = 0; jp < 4; ++jp) {
#pragma unroll
            for (int i = 0; i < 4; ++i) {
                mma16816(acc[i][2 * jp],     ah[p][i], bh[p][jp][0], bh[p][jp][1]);
                mma16816(acc[i][2 * jp + 1], ah[p][i], bh[p][jp][2], bh[p][jp][3]);
            }
        }
    }

    // epilogue: silu(gate)*up -> h1 as fp16
#pragma unroll
    for (int i = 0; i < 4; ++i) {
        const int r0l = wm * 64 + i * 16 + (lane >> 2);
        const int r1l = r0l + 8;
#pragma unroll
        for (int jp = 0; jp < 4; ++jp) {
            const int col = f0 + (wn * 4 + jp) * 8 + (lane & 3) * 2;
            const float* gv = acc[i][2 * jp];
            const float* uv = acc[i][2 * jp + 1];
            if (m0 + r0l < cnt) {
                float o0 = (gv[0] / (1.f + __expf(-gv[0]))) * uv[0];
                float o1 = (gv[1] / (1.f + __expf(-gv[1]))) * uv[1];
                const size_t p = (size_t)(off + m0 + r0l) * NF + col;
                *(uint32_t*)(g_h1h + p) = h2u(__floats2half2_rn(o0, o1));
            }
            if (m0 + r1l < cnt) {
                float o2 = (gv[2] / (1.f + __expf(-gv[2]))) * uv[2];
                float o3 = (gv[3] / (1.f + __expf(-gv[3]))) * uv[3];
                const size_t p = (size_t)(off + m0 + r1l) * NF + col;
                *(uint32_t*)(g_h1h + p) = h2u(__floats2half2_rn(o2, o3));
            }
        }
    }
}

// ---------------- GEMM2: fp16 mma, cp.async + register double-buffer --------
// CTA tile: 128 pairs x 256 H-cols.
__global__ void __launch_bounds__(256)
gemm2_k(const float* __restrict__ db) {
    const int e   = blockIdx.z;
    const int cnt = g_counts[e];
    const int m0  = blockIdx.x * 128;
    if (m0 >= cnt) return;
    const int off = g_offsets[e];
    const int n0  = blockIdx.y * 256;

    extern __shared__ char smem[];
    const uint32_t sb = s2u(smem);
    const int tid  = threadIdx.x;
    const int wid  = tid >> 5;
    const int lane = tid & 31;
    const int wm = wid >> 2, wn = wid & 3;

    const int lrow = tid >> 1;
    const int half = tid & 1;
    int mrow = m0 + lrow; if (mrow >= cnt) mrow = cnt - 1;
    const __half* axh = g_h1h + (size_t)(off + mrow) * NF + half * 8;
    const __half* bw0 = g_wdh + ((size_t)e * NH + n0 + lrow) * NF + half * 8;
    const __half* bw1 = g_wdh + ((size_t)e * NH + n0 + 128 + lrow) * NF + half * 8;
    const uint32_t a_soff  = lrow * TROW + half * 16;
    const uint32_t b_soff0 = lrow * TROW + half * 16;
    const uint32_t b_soff1 = (128 + lrow) * TROW + half * 16;

    float acc[4][8][4];
#pragma unroll
    for (int i = 0; i < 4; ++i)
#pragma unroll
        for (int j = 0; j < 8; ++j)
#pragma unroll
            for (int q = 0; q < 4; ++q) acc[i][j][q] = 0.f;

    const int NCH = NF / 16;   // 352
#pragma unroll
    for (int s = 0; s < 3; ++s) {
        const uint32_t st = sb + s * STAGE;
        const int k = s * 16;
        cpa16(st + OAH + a_soff, axh + k);
        cpa16(st + OBH + b_soff0, bw0 + k);
        cpa16(st + OBH + b_soff1, bw1 + k);
        CPA_COMMIT();
    }

    const uint32_t afr = (wm * 64 + (lane & 15)) * TROW + (lane >> 4) * 16;
    const uint32_t bfr = (wn * 64 + ((lane >> 4) << 3) + (lane & 7)) * TROW + ((lane >> 3) & 1) * 16;

    uint32_t ah[2][4][4], bh[2][4][4];
    CPA_WAIT2();
    __syncthreads();
#pragma unroll
    for (int i = 0; i < 4; ++i) ldmx4(ah[0][i], sb + OAH + afr + i * 16 * TROW);
#pragma unroll
    for (int jp = 0; jp < 4; ++jp) ldmx4(bh[0][jp], sb + OBH + bfr + jp * 16 * TROW);

    for (int c = 0; c < NCH; ++c) {
        const int p = c & 1;
        CPA_WAIT1();
        __syncthreads();

        if (c + 3 < NCH) {
            const uint32_t st = sb + ((c + 3) & 3) * STAGE;
            const int k = (c + 3) * 16;
            cpa16(st + OAH + a_soff, axh + k);
            cpa16(st + OBH + b_soff0, bw0 + k);
            cpa16(st + OBH + b_soff1, bw1 + k);
        }
        CPA_COMMIT();

        if (c + 1 < NCH) {
            const uint32_t st = sb + ((c + 1) & 3) * STAGE;
#pragma unroll
            for (int i = 0; i < 4; ++i) ldmx4(ah[1 - p][i], st + OAH + afr + i * 16 * TROW);
#pragma unroll
            for (int jp = 0; jp < 4; ++jp) ldmx4(bh[1 - p][jp], st + OBH + bfr + jp * 16 * TROW);
        }

#pragma unroll
        for (int jp = 0; jp < 4; ++jp) {
#pragma unroll
            for (int i = 0; i < 4; ++i) {
                mma16816(acc[i][2 * jp],     ah[p][i], bh[p][jp][0], bh[p][jp][1]);
                mma16816(acc[i][2 * jp + 1], ah[p][i], bh[p][jp][2], bh[p][jp][3]);
            }
        }
    }

#pragma unroll
    for (int i = 0; i < 4; ++i) {
        const int r0l = wm * 64 + i * 16 + (lane >> 2);
        const int r1l = r0l + 8;
#pragma unroll
        for (int j = 0; j < 8; ++j) {
            const int col = n0 + wn * 64 + j * 8 + (lane & 3) * 2;
            const float b0 = db[(size_t)e * NH + col];
            const float b1 = db[(size_t)e * NH + col + 1];
            if (m0 + r0l < cnt)
                *(uint32_t*)(g_hoh + (size_t)(off + m0 + r0l) * NH + col) =
                    h2u(__floats2half2_rn(acc[i][j][0] + b0, acc[i][j][1] + b1));
            if (m0 + r1l < cnt)
                *(uint32_t*)(g_hoh + (size_t)(off + m0 + r1l) * NH + col) =
                    h2u(__floats2half2_rn(acc[i][j][2] + b0, acc[i][j][3] + b1));
        }
    }
}

// ---------------- combine ----------------------------------------------------
__global__ void combine_k(const float* __restrict__ res, float* __restrict__ out) {
    const int idx = blockIdx.x * blockDim.x + threadIdx.x;
    const int NV  = NT * NH / 4;
    if (idx >= NV) return;
    const int t = idx >> 9;
    const int c = idx & 511;
    const int p0 = g_token_pair[2 * t + 0];
    const int p1 = g_token_pair[2 * t + 1];
    const float w0 = g_top_w[2 * t + 0];
    const float w1 = g_top_w[2 * t + 1];
    const float4 r = ((const float4*)res)[idx];
    const __half2* ap = (const __half2*)(g_hoh + (size_t)p0 * NH) + 2 * c;
    const __half2* bp = (const __half2*)(g_hoh + (size_t)p1 * NH) + 2 * c;
    float2 a0 = __half22float2(ap[0]), a1 = __half22float2(ap[1]);
    float2 b0 = __half22float2(bp[0]), b1 = __half22float2(bp[1]);
    float4 o;
    o.x = r.x + w0 * a0.x + w1 * b0.x;
    o.y = r.y + w0 * a0.y + w1 * b0.y;
    o.z = r.z + w0 * a1.x + w1 * b1.x;
    o.w = r.w + w0 * a1.y + w1 * b1.y;
    ((float4*)out)[idx] = o;
}

// ---------------- launch ----------------------------------------------------
extern "C" void kernel_launch(void* const* d_in, const int* in_sizes, int n_in,
                              void* d_out, int out_size) {
    const float* x    = (const float*)d_in[0];
    const float* res  = (const float*)d_in[1];
    const float* rW   = (const float*)d_in[2];
    const float* gW   = (const float*)d_in[3];
    const float* uW   = (const float*)d_in[4];
    const float* dW   = (const float*)d_in[5];
    const float* db   = (const float*)d_in[6];
    const int*   elim = (const int*)d_in[7];

    float* out    = (float*)d_out;
    float* logits = out + (size_t)NT * NH;

    cudaFuncSetAttribute(gemm1_k, cudaFuncAttributeMaxDynamicSharedMemorySize, GSMEM);
    cudaFuncSetAttribute(gemm2_k, cudaFuncAttributeMaxDynamicSharedMemorySize, GSMEM);

    init_k<<<1, 32>>>();
    router_k<<<NT / 8, 256>>>(x, rW, elim, logits);
    scan_k<<<1, 32>>>();
    scatter_k<<<NT / 256, 256>>>();

    const size_t nw1 = (size_t)NE * NF * (NH / 8);
    cvtw1_k<<<(unsigned)((nw1 + 255) / 256), 256>>>(gW, uW);
    const size_t nwd = (size_t)NE * NH * (NF / 8);
    cvtwd_k<<<(unsigned)((nwd + 255) / 256), 256>>>(dW);
    const size_t nx = (size_t)NT * (NH / 8);
    cvtx_k<<<(unsigned)((nx + 255) / 256), 256>>>(x);

    gemm1_k<<<dim3(NT / 128, NF / 128, NE), 256, GSMEM>>>();
    gemm2_k<<<dim3(NT / 128, NH / 256, NE), 256, GSMEM>>>(db);
    combine_k<<<(NT * NH / 4 + 255) / 256, 256>>>(res, out);
}